// round 12
// baseline (speedup 1.0000x reference)
#include <cuda_runtime.h>
#include <cuda_fp16.h>
#include <math.h>
#include <stdint.h>

#define NROWS    8192
#define DIM      1024
#define NCLASSES 50257
#define CUT0     4000
#define CUT1     20000
#define MGUARD   20.0f

#define MT  128
#define NT  128
#define BK  64
#define NCH (DIM / BK)            /* 16 k-chunks */
#define RT  (NROWS / MT)          /* 64 row tiles */
#define COLS_PAD 50688

#define YT_HEAD 32
#define YT_T1   125
#define YT_T2   237

#define STAGE_BYTES 32768         /* A 16KB + B 16KB per stage */
#define NSTAGE 2
#define SM_TOTAL (NSTAGE * STAGE_BYTES)     /* 64KB -> 3 CTAs/SM */

#define NPERSIST 456              /* 152 SMs x 3 CTAs */

#define SW128(o) ((o) ^ (((o) >> 3) & 0x70))

/* prep kernel block partition */
#define CVTW_BLOCKS (((long)COLS_PAD * DIM / 16 + 255) / 256)   /* 12672 */
#define CVTA_BLOCKS (((long)NROWS * DIM / 16 + 255) / 256)      /* 2048 */
#define CLS_BLOCKS  (NROWS / 256)                               /* 32 */
#define PREP_BLOCKS (CVTW_BLOCKS + CVTA_BLOCKS + CLS_BLOCKS)

// ---------------- device scratch ----------------
__device__ __align__(256) __half g_A16[(size_t)NROWS * DIM];
__device__ __align__(256) __half g_W16[(size_t)COLS_PAD * DIM];
__device__ float g_head[NROWS];
__device__ float g_t1[NROWS];
__device__ float g_t2[NROWS];
__device__ int   g_rows_c1[NROWS];
__device__ int   g_rows_c2[NROWS];
__device__ int   g_cnt[2];
__device__ int   g_work;

// ---------------- PTX helpers ----------------
__device__ __forceinline__ uint32_t smem_u32(const void* p) {
    uint32_t a;
    asm("{ .reg .u64 t; cvta.to.shared.u64 t, %1; cvt.u32.u64 %0, t; }" : "=r"(a) : "l"(p));
    return a;
}
__device__ __forceinline__ void cp16(uint32_t dst, const void* src) {
    asm volatile("cp.async.cg.shared.global [%0], [%1], 16;" :: "r"(dst), "l"(src) : "memory");
}
__device__ __forceinline__ void cp_commit() {
    asm volatile("cp.async.commit_group;" ::: "memory");
}
template <int N>
__device__ __forceinline__ void cp_wait() {
    asm volatile("cp.async.wait_group %0;" :: "n"(N) : "memory");
}
__device__ __forceinline__ void ldm_x4(uint32_t* r, uint32_t addr) {
    asm volatile("ldmatrix.sync.aligned.m8n8.x4.shared.b16 {%0,%1,%2,%3}, [%4];"
                 : "=r"(r[0]), "=r"(r[1]), "=r"(r[2]), "=r"(r[3]) : "r"(addr));
}
__device__ __forceinline__ void ldm_x4_t(uint32_t* r, uint32_t addr) {
    asm volatile("ldmatrix.sync.aligned.m8n8.x4.trans.shared.b16 {%0,%1,%2,%3}, [%4];"
                 : "=r"(r[0]), "=r"(r[1]), "=r"(r[2]), "=r"(r[3]) : "r"(addr));
}
__device__ __forceinline__ void mma_fp16h(uint32_t* c, const uint32_t* a, const uint32_t* b) {
    asm volatile(
        "mma.sync.aligned.m16n8k16.row.col.f16.f16.f16.f16 "
        "{%0,%1}, {%2,%3,%4,%5}, {%6,%7}, {%0,%1};"
        : "+r"(c[0]), "+r"(c[1])
        : "r"(a[0]), "r"(a[1]), "r"(a[2]), "r"(a[3]), "r"(b[0]), "r"(b[1]));
}

// ---------------- init ----------------
__global__ void init_kernel(float* out, int out_size) {
    int i = blockIdx.x * blockDim.x + threadIdx.x;
    if (i < NROWS) { g_head[i] = 0.f; g_t1[i] = 0.f; g_t2[i] = 0.f; }
    if (i < 2) g_cnt[i] = 0;
    if (i == 0) g_work = 0;
    if (i == 1 && out_size > NROWS) out[NROWS] = 0.f;
}

// ---------------- prep: weight-cvt + input-cvt + classify ----------------
__device__ __forceinline__ uint32_t pack2hf(float a, float b) {
    __half2 t = __floats2half2_rn(a, b);
    return *reinterpret_cast<uint32_t*>(&t);
}
__device__ __forceinline__ void cvt16(const float* __restrict__ src, __half* __restrict__ dst,
                                      long i, long n_src) {
    uint4 o;
    if (i < n_src) {
        float4 v0 = ((const float4*)src)[i / 4];
        float4 v1 = ((const float4*)src)[i / 4 + 1];
        float4 v2 = ((const float4*)src)[i / 4 + 2];
        float4 v3 = ((const float4*)src)[i / 4 + 3];
        uint4 p;
        p.x = pack2hf(v0.x, v0.y); p.y = pack2hf(v0.z, v0.w);
        p.z = pack2hf(v1.x, v1.y); p.w = pack2hf(v1.z, v1.w);
        o = p;
        *((uint4*)(dst + i)) = o;
        p.x = pack2hf(v2.x, v2.y); p.y = pack2hf(v2.z, v2.w);
        p.z = pack2hf(v3.x, v3.y); p.w = pack2hf(v3.z, v3.w);
        *((uint4*)(dst + i + 8)) = p;
    } else {
        o = make_uint4(0, 0, 0, 0);
        *((uint4*)(dst + i)) = o;
        *((uint4*)(dst + i + 8)) = o;
    }
}
__global__ void prep_kernel(const float* __restrict__ input,
                            const float* __restrict__ weight,
                            const int*   __restrict__ target) {
    long bx = blockIdx.x;
    if (bx < CVTW_BLOCKS) {
        long i = (bx * 256 + threadIdx.x) * 16;
        if (i < (long)COLS_PAD * DIM)
            cvt16(weight, g_W16, i, (long)NCLASSES * DIM);
    } else if (bx < CVTW_BLOCKS + CVTA_BLOCKS) {
        long i = ((bx - CVTW_BLOCKS) * 256 + threadIdx.x) * 16;
        if (i < (long)NROWS * DIM)
            cvt16(input, g_A16, i, (long)NROWS * DIM);
    } else {
        int r = (int)(bx - CVTW_BLOCKS - CVTA_BLOCKS) * 256 + threadIdx.x;
        if (r < NROWS) {
            int t = target[r];
            if (t >= CUT1)      { int p = atomicAdd(&g_cnt[1], 1); g_rows_c2[p] = r; }
            else if (t >= CUT0) { int p = atomicAdd(&g_cnt[0], 1); g_rows_c1[p] = r; }
        }
    }
}

// ---------------- persistent fused HMMA exp-sum GEMM ----------------
// 456 persistent CTAs pull tile ids from g_work. Tile = 128 rows x 128 cols,
// 256 threads (2 M x 4 N warps, warp 64x32), BK=64, 2-stage cp.async,
// fp16 accumulators, 3 CTAs/SM.
__global__ void __launch_bounds__(256, 3)
hmma_persist(const float* __restrict__ bias)
{
    extern __shared__ char smem[];
    __shared__ int s_t;
    const uint32_t sb = smem_u32(smem);
    const int tid = threadIdx.x;
    const int wid = tid >> 5;
    const int lane = tid & 31;

    const int cnt1 = g_cnt[0];
    const int cnt2 = g_cnt[1];
    const int nt1 = (cnt1 + MT - 1) >> 7;
    const int nt2 = (cnt2 + MT - 1) >> 7;
    const int T0 = RT * YT_HEAD;                 /* 2048 */
    const int T1 = T0 + nt1 * YT_T1;
    const int T2 = T1 + nt2 * YT_T2;

    // loop-invariant warp fragment addressing
    const int wm = wid & 1;
    const int wn = wid >> 1;
    const int arow = wm * 64 + (lane & 15);
    const uint32_t a_xor = (arow & 7) << 4;
    const uint32_t a_kext = (lane >> 4) << 4;
    const int ln = lane & 7, sel = lane >> 3;
    const int brow = wn * 32 + ln + ((sel >> 1) << 3);
    const uint32_t b_xor = (uint32_t)ln << 4;
    const uint32_t b_kext = (sel & 1) << 4;
    const int r_a = tid >> 3;
    const int kc  = tid & 7;
    const uint32_t adst0 = sb + SW128(r_a * 128 + kc * 16);          // +4096/i
    const uint32_t bdst0 = sb + 16384 + SW128(r_a * 128 + kc * 16);  // +4096/i

    for (;;) {
        if (tid == 0) s_t = atomicAdd(&g_work, 1);
        __syncthreads();              // broadcast s_t; also fences epilogue red[] reads
        const int t = s_t;
        if (t >= T2) break;

        // ---- decode tile (coltile-major within each region for B reuse) ----
        int row0, col0, col_hi, cnt;
        const int* rowlist;
        float* acc;
        if (t < T0) {
            col0 = (t >> 6) * NT; col_hi = CUT0;
            row0 = (t & 63) * MT; cnt = NROWS; rowlist = nullptr; acc = g_head;
        } else if (t < T1) {
            int u = t - T0;
            int ct = u / nt1;
            col0 = CUT0 + ct * NT; col_hi = CUT1;
            row0 = (u - ct * nt1) * MT; cnt = cnt1; rowlist = g_rows_c1; acc = g_t1;
        } else {
            int u = t - T1;
            int ct = u / nt2;
            col0 = CUT1 + ct * NT; col_hi = NCLASSES;
            row0 = (u - ct * nt2) * MT; cnt = cnt2; rowlist = g_rows_c2; acc = g_t2;
        }

        // ---- per-tile A row gather ----
        int arow_idx[4];
#pragma unroll
        for (int i = 0; i < 4; i++) {
            int rr = row0 + r_a + 32 * i;
            if (rowlist) arow_idx[i] = rowlist[rr < cnt ? rr : cnt - 1];
            else         arow_idx[i] = rr;
        }
        const __half* bsrc0 = g_W16 + (size_t)(col0 + r_a) * DIM + kc * 8;

        // prologue: stages 0,1
#pragma unroll
        for (int s = 0; s < 2; s++) {
            const uint32_t st = s * STAGE_BYTES;
            const int kof = s * BK;
#pragma unroll
            for (int i = 0; i < 4; i++) {
                cp16(adst0 + 4096 * i + st, g_A16 + (size_t)arow_idx[i] * DIM + kc * 8 + kof);
                cp16(bdst0 + 4096 * i + st, bsrc0 + (size_t)32 * DIM * i + kof);
            }
            cp_commit();
        }

        uint32_t hfr[4][4][2];
#pragma unroll
        for (int mi = 0; mi < 4; mi++)
#pragma unroll
            for (int ni = 0; ni < 4; ni++) { hfr[mi][ni][0] = 0u; hfr[mi][ni][1] = 0u; }

        for (int ch = 0; ch < NCH; ch++) {
            if (ch < NCH - 1) cp_wait<1>(); else cp_wait<0>();
            __syncthreads();

            const uint32_t st = (ch & 1) * STAGE_BYTES;
            const uint32_t Ab = sb + st + (uint32_t)arow * 128;
            const uint32_t Bb = sb + st + 16384 + (uint32_t)brow * 128;

#pragma unroll
            for (int kk = 0; kk < 4; kk++) {
                uint32_t a[4][4], b[2][4];
                const uint32_t kbA = (kk * 32 + a_kext) ^ a_xor;
                const uint32_t kbB = (kk * 32 + b_kext) ^ b_xor;
#pragma unroll
                for (int mi = 0; mi < 4; mi++)
                    ldm_x4(a[mi], Ab + mi * 2048 + kbA);
#pragma unroll
                for (int nt = 0; nt < 2; nt++)
                    ldm_x4_t(b[nt], Bb + nt * 2048 + kbB);
#pragma unroll
                for (int mi = 0; mi < 4; mi++)
#pragma unroll
                    for (int ni = 0; ni < 4; ni++)
                        mma_fp16h(hfr[mi][ni], a[mi], &b[ni >> 1][(ni & 1) * 2]);
            }
            __syncthreads();

            if (ch + 2 < NCH) {
                const int kof = (ch + 2) * BK;
#pragma unroll
                for (int i = 0; i < 4; i++) {
                    cp16(adst0 + 4096 * i + st, g_A16 + (size_t)arow_idx[i] * DIM + kc * 8 + kof);
                    cp16(bdst0 + 4096 * i + st, bsrc0 + (size_t)32 * DIM * i + kof);
                }
                cp_commit();
            }
        }

        // ---- epilogue ----
        float* red = (float*)smem;
        if (tid < MT) red[tid] = 0.f;
        __syncthreads();

#pragma unroll
        for (int mi = 0; mi < 4; mi++) {
            const int rl = wm * 64 + mi * 16 + (lane >> 2);
            float s0 = 0.f, s1 = 0.f;
#pragma unroll
            for (int ni = 0; ni < 4; ni++) {
                const int cc = col0 + wn * 32 + ni * 8 + (lane & 3) * 2;
                float2 f01 = __half22float2(*(const __half2*)&hfr[mi][ni][0]);
                float2 f23 = __half22float2(*(const __half2*)&hfr[mi][ni][1]);
                if (cc < col_hi) {
                    float bb = bias[cc];
                    s0 += __expf(f01.x + bb - MGUARD);
                    s1 += __expf(f23.x + bb - MGUARD);
                }
                if (cc + 1 < col_hi) {
                    float bb = bias[cc + 1];
                    s0 += __expf(f01.y + bb - MGUARD);
                    s1 += __expf(f23.y + bb - MGUARD);
                }
            }
            s0 += __shfl_xor_sync(0xffffffffu, s0, 1);
            s0 += __shfl_xor_sync(0xffffffffu, s0, 2);
            s1 += __shfl_xor_sync(0xffffffffu, s1, 1);
            s1 += __shfl_xor_sync(0xffffffffu, s1, 2);
            if ((lane & 3) == 0) {
                atomicAdd(&red[rl], s0);
                atomicAdd(&red[rl + 8], s1);
            }
        }
        __syncthreads();

        if (tid < MT) {
            int rr = row0 + tid;
            if (rr < cnt) {
                int orow = rowlist ? rowlist[rr] : rr;
                atomicAdd(&acc[orow], red[tid]);
            }
        }
        // loop-top __syncthreads() protects red[] before next prologue
    }
}

// ---------------- finalize ----------------
__global__ void __launch_bounds__(256)
finalize_kernel(const float* __restrict__ A,
                const int*   __restrict__ target,
                const float* __restrict__ W,
                const float* __restrict__ bias,
                const float* __restrict__ TV,
                const float* __restrict__ TB,
                float* __restrict__ out, int out_size)
{
    int gwarp = (blockIdx.x * blockDim.x + threadIdx.x) >> 5;
    int lane = threadIdx.x & 31;
    if (gwarp >= NROWS) return;
    int r = gwarp;
    int t = target[r];

    const float4* a4   = (const float4*)(A + (size_t)r * DIM);
    const float4* wt4  = (const float4*)(W + (size_t)t * DIM);
    const float4* tv04 = (const float4*)(TV);
    const float4* tv14 = (const float4*)(TV + DIM);

    float dwt = 0.f, d0 = 0.f, d1 = 0.f;
#pragma unroll
    for (int it = 0; it < DIM / 128; it++) {
        int i = lane + it * 32;
        float4 a = a4[i], w = wt4[i], v0 = tv04[i], v1 = tv14[i];
        dwt += a.x * w.x  + a.y * w.y  + a.z * w.z  + a.w * w.w;
        d0  += a.x * v0.x + a.y * v0.y + a.z * v0.z + a.w * v0.w;
        d1  += a.x * v1.x + a.y * v1.y + a.z * v1.z + a.w * v1.w;
    }
#pragma unroll
    for (int o = 16; o > 0; o >>= 1) {
        dwt += __shfl_xor_sync(0xffffffffu, dwt, o);
        d0  += __shfl_xor_sync(0xffffffffu, d0,  o);
        d1  += __shfl_xor_sync(0xffffffffu, d1,  o);
    }

    if (lane == 0) {
        float tv0l = d0 + TB[0];
        float tv1l = d1 + TB[1];
        float head_sum = g_head[r] + __expf(tv0l - MGUARD) + __expf(tv1l - MGUARD);
        float head_lse = logf(head_sum) + MGUARD;

        int c = (t >= CUT0) + (t >= CUT1);
        float wt_logit = dwt + bias[t];
        float gather = (c == 0) ? wt_logit : ((c == 1) ? tv0l : tv1l);
        float head_term = gather - head_lse;

        float tail_term = 0.f;
        if (c > 0) {
            float ts = (c == 1) ? g_t1[r] : g_t2[r];
            tail_term = wt_logit - (logf(ts) + MGUARD);
        }
        float o = head_term + tail_term;
        if (r < out_size) out[r] = o;
        if (out_size > NROWS) atomicAdd(&out[NROWS], -o / (float)NROWS);
    }
}

// ---------------- launch ----------------
extern "C" void kernel_launch(void* const* d_in, const int* in_sizes, int n_in,
                              void* d_out, int out_size)
{
    const float* input  = (const float*)d_in[0];
    const int*   target = (const int*)  d_in[1];
    const float* weight = (const float*)d_in[2];
    const float* bias   = (const float*)d_in[3];
    const float* tvec   = (const float*)d_in[4];
    const float* tbias  = (const float*)d_in[5];
    float* out = (float*)d_out;

    cudaFuncSetAttribute(hmma_persist, cudaFuncAttributeMaxDynamicSharedMemorySize, SM_TOTAL);

    init_kernel<<<(NROWS + 255) / 256, 256>>>(out, out_size);
    prep_kernel<<<(int)PREP_BLOCKS, 256>>>(input, weight, target);

    hmma_persist<<<NPERSIST, 256, SM_TOTAL>>>(bias);

    finalize_kernel<<<(NROWS * 32 + 255) / 256, 256>>>(
        input, target, weight, bias, tvec, tbias, out, out_size);
}

// round 13
// speedup vs baseline: 1.2783x; 1.2783x over previous
#include <cuda_runtime.h>
#include <cuda_fp16.h>
#include <math.h>
#include <stdint.h>

#define NROWS    8192
#define DIM      1024
#define NCLASSES 50257
#define CUT0     4000
#define CUT1     20000
#define MGUARD   20.0f

#define MT  128
#define NT  128
#define BK  64
#define NCH (DIM / BK)            /* 16 k-chunks */
#define RT  (NROWS / MT)          /* 64 row tiles */
#define COLS_PAD 50688

#define YT_HEAD 32
#define YT_T1   125
#define YT_T2   237
#define YTOT    (YT_HEAD + YT_T1 + YT_T2)   /* 394 */

#define STAGE_BYTES 32768         /* A 16KB + B 16KB per stage */
#define NSTAGE 2
#define SM_TOTAL (NSTAGE * STAGE_BYTES)     /* 64KB -> 3 CTAs/SM */

#define SW128(o) ((o) ^ (((o) >> 3) & 0x70))

/* prep kernel block partition */
#define CVTW_BLOCKS (((long)COLS_PAD * DIM / 16 + 255) / 256)   /* 12672 */
#define CVTA_BLOCKS (((long)NROWS * DIM / 16 + 255) / 256)      /* 2048 */
#define CLS_BLOCKS  (NROWS / 256)                               /* 32 */
#define DOT_BLOCKS  (NROWS / 8)                                 /* 1024: 8 rows/block */
#define PREP_BLOCKS (CVTW_BLOCKS + CVTA_BLOCKS + CLS_BLOCKS + DOT_BLOCKS)

// ---------------- device scratch ----------------
__device__ __align__(256) __half g_A16[(size_t)NROWS * DIM];
__device__ __align__(256) __half g_W16[(size_t)COLS_PAD * DIM];
__device__ float g_head[NROWS];
__device__ float g_t1[NROWS];
__device__ float g_t2[NROWS];
__device__ float g_dwt[NROWS];
__device__ float g_d0[NROWS];
__device__ float g_d1[NROWS];
__device__ int   g_rows_c1[NROWS];
__device__ int   g_rows_c2[NROWS];
__device__ int   g_cnt[2];

// ---------------- PTX helpers ----------------
__device__ __forceinline__ uint32_t smem_u32(const void* p) {
    uint32_t a;
    asm("{ .reg .u64 t; cvta.to.shared.u64 t, %1; cvt.u32.u64 %0, t; }" : "=r"(a) : "l"(p));
    return a;
}
__device__ __forceinline__ void cp16(uint32_t dst, const void* src) {
    asm volatile("cp.async.cg.shared.global [%0], [%1], 16;" :: "r"(dst), "l"(src) : "memory");
}
__device__ __forceinline__ void cp_commit() {
    asm volatile("cp.async.commit_group;" ::: "memory");
}
template <int N>
__device__ __forceinline__ void cp_wait() {
    asm volatile("cp.async.wait_group %0;" :: "n"(N) : "memory");
}
__device__ __forceinline__ void ldm_x4(uint32_t* r, uint32_t addr) {
    asm volatile("ldmatrix.sync.aligned.m8n8.x4.shared.b16 {%0,%1,%2,%3}, [%4];"
                 : "=r"(r[0]), "=r"(r[1]), "=r"(r[2]), "=r"(r[3]) : "r"(addr));
}
__device__ __forceinline__ void ldm_x4_t(uint32_t* r, uint32_t addr) {
    asm volatile("ldmatrix.sync.aligned.m8n8.x4.trans.shared.b16 {%0,%1,%2,%3}, [%4];"
                 : "=r"(r[0]), "=r"(r[1]), "=r"(r[2]), "=r"(r[3]) : "r"(addr));
}
// fp16-accumulate HMMA (element positions match f32 variant's c0..c3)
__device__ __forceinline__ void mma_fp16h(uint32_t* c, const uint32_t* a, const uint32_t* b) {
    asm volatile(
        "mma.sync.aligned.m16n8k16.row.col.f16.f16.f16.f16 "
        "{%0,%1}, {%2,%3,%4,%5}, {%6,%7}, {%0,%1};"
        : "+r"(c[0]), "+r"(c[1])
        : "r"(a[0]), "r"(a[1]), "r"(a[2]), "r"(a[3]), "r"(b[0]), "r"(b[1]));
}

// ---------------- init ----------------
__global__ void init_kernel(float* out, int out_size) {
    int i = blockIdx.x * blockDim.x + threadIdx.x;
    if (i < NROWS) { g_head[i] = 0.f; g_t1[i] = 0.f; g_t2[i] = 0.f; }
    if (i < 2) g_cnt[i] = 0;
    if (i == 0 && out_size > NROWS) out[NROWS] = 0.f;
}

// ---------------- prep: weight-cvt + input-cvt + classify + row dots ----------------
__device__ __forceinline__ uint32_t pack2hf(float a, float b) {
    __half2 t = __floats2half2_rn(a, b);
    return *reinterpret_cast<uint32_t*>(&t);
}
__device__ __forceinline__ void cvt16(const float* __restrict__ src, __half* __restrict__ dst,
                                      long i, long n_src) {
    uint4 o;
    if (i < n_src) {
        float4 v0 = ((const float4*)src)[i / 4];
        float4 v1 = ((const float4*)src)[i / 4 + 1];
        float4 v2 = ((const float4*)src)[i / 4 + 2];
        float4 v3 = ((const float4*)src)[i / 4 + 3];
        uint4 p;
        p.x = pack2hf(v0.x, v0.y); p.y = pack2hf(v0.z, v0.w);
        p.z = pack2hf(v1.x, v1.y); p.w = pack2hf(v1.z, v1.w);
        o = p;
        *((uint4*)(dst + i)) = o;
        p.x = pack2hf(v2.x, v2.y); p.y = pack2hf(v2.z, v2.w);
        p.z = pack2hf(v3.x, v3.y); p.w = pack2hf(v3.z, v3.w);
        *((uint4*)(dst + i + 8)) = p;
    } else {
        o = make_uint4(0, 0, 0, 0);
        *((uint4*)(dst + i)) = o;
        *((uint4*)(dst + i + 8)) = o;
    }
}
__global__ void prep_kernel(const float* __restrict__ input,
                            const float* __restrict__ weight,
                            const int*   __restrict__ target,
                            const float* __restrict__ tvec) {
    long bx = blockIdx.x;
    if (bx < CVTW_BLOCKS) {
        long i = (bx * 256 + threadIdx.x) * 16;
        if (i < (long)COLS_PAD * DIM)
            cvt16(weight, g_W16, i, (long)NCLASSES * DIM);
    } else if (bx < CVTW_BLOCKS + CVTA_BLOCKS) {
        long i = ((bx - CVTW_BLOCKS) * 256 + threadIdx.x) * 16;
        if (i < (long)NROWS * DIM)
            cvt16(input, g_A16, i, (long)NROWS * DIM);
    } else if (bx < CVTW_BLOCKS + CVTA_BLOCKS + CLS_BLOCKS) {
        int r = (int)(bx - CVTW_BLOCKS - CVTA_BLOCKS) * 256 + threadIdx.x;
        if (r < NROWS) {
            int t = target[r];
            if (t >= CUT1)      { int p = atomicAdd(&g_cnt[1], 1); g_rows_c2[p] = r; }
            else if (t >= CUT0) { int p = atomicAdd(&g_cnt[0], 1); g_rows_c1[p] = r; }
        }
    } else {
        // per-row fp32 dots: input . weight[target], input . tail_vec0/1
        int r = (int)(bx - CVTW_BLOCKS - CVTA_BLOCKS - CLS_BLOCKS) * 8 + (threadIdx.x >> 5);
        int lane = threadIdx.x & 31;
        int t = target[r];
        const float4* a4   = (const float4*)(input + (size_t)r * DIM);
        const float4* wt4  = (const float4*)(weight + (size_t)t * DIM);
        const float4* tv04 = (const float4*)(tvec);
        const float4* tv14 = (const float4*)(tvec + DIM);
        float dwt = 0.f, d0 = 0.f, d1 = 0.f;
        for (int i = lane; i < DIM / 4; i += 32) {
            float4 a = a4[i], w = wt4[i], v0 = tv04[i], v1 = tv14[i];
            dwt += a.x * w.x  + a.y * w.y  + a.z * w.z  + a.w * w.w;
            d0  += a.x * v0.x + a.y * v0.y + a.z * v0.z + a.w * v0.w;
            d1  += a.x * v1.x + a.y * v1.y + a.z * v1.z + a.w * v1.w;
        }
#pragma unroll
        for (int o = 16; o > 0; o >>= 1) {
            dwt += __shfl_xor_sync(0xffffffffu, dwt, o);
            d0  += __shfl_xor_sync(0xffffffffu, d0,  o);
            d1  += __shfl_xor_sync(0xffffffffu, d1,  o);
        }
        if (lane == 0) { g_dwt[r] = dwt; g_d0[r] = d0; g_d1[r] = d1; }
    }
}

// ---------------- fused HMMA exp-sum GEMM (exact R11 body) ----------------
__global__ void __launch_bounds__(256, 3)
hmma_fused(const float* __restrict__ bias)
{
    extern __shared__ char smem[];
    const uint32_t sb = smem_u32(smem);
    const int tid = threadIdx.x;
    const int wid = tid >> 5;
    const int lane = tid & 31;

    // ---- region decode ----
    int ty = blockIdx.y;
    int col_lo, col_hi;
    const int* rowlist;
    int cnt;
    float* acc;
    if (ty < YT_HEAD) {
        col_lo = 0; col_hi = CUT0; rowlist = nullptr; cnt = NROWS; acc = g_head;
    } else if (ty < YT_HEAD + YT_T1) {
        ty -= YT_HEAD;
        col_lo = CUT0; col_hi = CUT1; rowlist = g_rows_c1; cnt = g_cnt[0]; acc = g_t1;
    } else {
        ty -= YT_HEAD + YT_T1;
        col_lo = CUT1; col_hi = NCLASSES; rowlist = g_rows_c2; cnt = g_cnt[1]; acc = g_t2;
    }
    const int row0 = blockIdx.x * MT;
    if (row0 >= cnt) return;
    const int col0 = col_lo + ty * NT;

    // ---- compact cp.async setup ----
    const int r_a = tid >> 3;
    const int kc  = tid & 7;
    int arow_idx[4];
#pragma unroll
    for (int i = 0; i < 4; i++) {
        int rr = row0 + (tid >> 3) + 32 * i;
        if (rowlist) arow_idx[i] = rowlist[rr < cnt ? rr : cnt - 1];
        else         arow_idx[i] = rr;
    }
    const __half* bsrc0 = g_W16 + (size_t)(col0 + r_a) * DIM + kc * 8;
    const uint32_t adst0 = sb + SW128(r_a * 128 + kc * 16);
    const uint32_t bdst0 = sb + 16384 + SW128(r_a * 128 + kc * 16);

    // prologue: stages 0,1
#pragma unroll
    for (int s = 0; s < 2; s++) {
        const uint32_t st = s * STAGE_BYTES;
        const int kof = s * BK;
#pragma unroll
        for (int i = 0; i < 4; i++) {
            cp16(adst0 + 4096 * i + st, g_A16 + (size_t)arow_idx[i] * DIM + kc * 8 + kof);
            cp16(bdst0 + 4096 * i + st, bsrc0 + (size_t)32 * DIM * i + kof);
        }
        cp_commit();
    }

    // ---- warp fragment addressing ----
    const int wm = wid & 1;
    const int wn = wid >> 1;
    const int arow = wm * 64 + (lane & 15);
    const uint32_t a_xor = (arow & 7) << 4;
    const uint32_t a_kext = (lane >> 4) << 4;
    const int ln = lane & 7, sel = lane >> 3;
    const int brow = wn * 32 + ln + ((sel >> 1) << 3);
    const uint32_t b_xor = (uint32_t)ln << 4;
    const uint32_t b_kext = (sel & 1) << 4;

    uint32_t hfr[4][4][2];
#pragma unroll
    for (int mi = 0; mi < 4; mi++)
#pragma unroll
        for (int ni = 0; ni < 4; ni++) { hfr[mi][ni][0] = 0u; hfr[mi][ni][1] = 0u; }

    for (int ch = 0; ch < NCH; ch++) {
        if (ch < NCH - 1) cp_wait<1>(); else cp_wait<0>();
        __syncthreads();

        const uint32_t st = (ch & 1) * STAGE_BYTES;
        const uint32_t Ab = sb + st + (uint32_t)arow * 128;
        const uint32_t Bb = sb + st + 16384 + (uint32_t)brow * 128;

#pragma unroll
        for (int kk = 0; kk < 4; kk++) {
            uint32_t a[4][4], b[2][4];
            const uint32_t kbA = (kk * 32 + a_kext) ^ a_xor;
            const uint32_t kbB = (kk * 32 + b_kext) ^ b_xor;
#pragma unroll
            for (int mi = 0; mi < 4; mi++)
                ldm_x4(a[mi], Ab + mi * 2048 + kbA);
#pragma unroll
            for (int nt = 0; nt < 2; nt++)
                ldm_x4_t(b[nt], Bb + nt * 2048 + kbB);
#pragma unroll
            for (int mi = 0; mi < 4; mi++)
#pragma unroll
                for (int ni = 0; ni < 4; ni++)
                    mma_fp16h(hfr[mi][ni], a[mi], &b[ni >> 1][(ni & 1) * 2]);
        }
        __syncthreads();

        if (ch + 2 < NCH) {
            const int kof = (ch + 2) * BK;
#pragma unroll
            for (int i = 0; i < 4; i++) {
                cp16(adst0 + 4096 * i + st, g_A16 + (size_t)arow_idx[i] * DIM + kc * 8 + kof);
                cp16(bdst0 + 4096 * i + st, bsrc0 + (size_t)32 * DIM * i + kof);
            }
            cp_commit();
        }
    }

    // ---- epilogue ----
    float* red = (float*)smem;
    if (tid < MT) red[tid] = 0.f;
    __syncthreads();

#pragma unroll
    for (int mi = 0; mi < 4; mi++) {
        const int rl = wm * 64 + mi * 16 + (lane >> 2);
        float s0 = 0.f, s1 = 0.f;
#pragma unroll
        for (int ni = 0; ni < 4; ni++) {
            const int cc = col0 + wn * 32 + ni * 8 + (lane & 3) * 2;
            float2 f01 = __half22float2(*(const __half2*)&hfr[mi][ni][0]);
            float2 f23 = __half22float2(*(const __half2*)&hfr[mi][ni][1]);
            if (cc < col_hi) {
                float bb = bias[cc];
                s0 += __expf(f01.x + bb - MGUARD);
                s1 += __expf(f23.x + bb - MGUARD);
            }
            if (cc + 1 < col_hi) {
                float bb = bias[cc + 1];
                s0 += __expf(f01.y + bb - MGUARD);
                s1 += __expf(f23.y + bb - MGUARD);
            }
        }
        s0 += __shfl_xor_sync(0xffffffffu, s0, 1);
        s0 += __shfl_xor_sync(0xffffffffu, s0, 2);
        s1 += __shfl_xor_sync(0xffffffffu, s1, 1);
        s1 += __shfl_xor_sync(0xffffffffu, s1, 2);
        if ((lane & 3) == 0) {
            atomicAdd(&red[rl], s0);
            atomicAdd(&red[rl + 8], s1);
        }
    }
    __syncthreads();

    if (tid < MT) {
        int rr = row0 + tid;
        if (rr < cnt) {
            int orow = rowlist ? rowlist[rr] : rr;
            atomicAdd(&acc[orow], red[tid]);
        }
    }
}

// ---------------- assemble: per-row combine (dots precomputed in prep) ----------------
__global__ void __launch_bounds__(256)
assemble_kernel(const int* __restrict__ target,
                const float* __restrict__ bias,
                const float* __restrict__ TB,
                float* __restrict__ out, int out_size)
{
    int r = blockIdx.x * blockDim.x + threadIdx.x;
    if (r >= NROWS) return;
    int t = target[r];

    float tv0l = g_d0[r] + TB[0];
    float tv1l = g_d1[r] + TB[1];
    float head_sum = g_head[r] + __expf(tv0l - MGUARD) + __expf(tv1l - MGUARD);
    float head_lse = logf(head_sum) + MGUARD;

    int c = (t >= CUT0) + (t >= CUT1);
    float wt_logit = g_dwt[r] + bias[t];
    float gather = (c == 0) ? wt_logit : ((c == 1) ? tv0l : tv1l);
    float head_term = gather - head_lse;

    float tail_term = 0.f;
    if (c > 0) {
        float ts = (c == 1) ? g_t1[r] : g_t2[r];
        tail_term = wt_logit - (logf(ts) + MGUARD);
    }
    float o = head_term + tail_term;
    if (r < out_size) out[r] = o;
    if (out_size > NROWS) atomicAdd(&out[NROWS], -o / (float)NROWS);
}

// ---------------- launch ----------------
extern "C" void kernel_launch(void* const* d_in, const int* in_sizes, int n_in,
                              void* d_out, int out_size)
{
    const float* input  = (const float*)d_in[0];
    const int*   target = (const int*)  d_in[1];
    const float* weight = (const float*)d_in[2];
    const float* bias   = (const float*)d_in[3];
    const float* tvec   = (const float*)d_in[4];
    const float* tbias  = (const float*)d_in[5];
    float* out = (float*)d_out;

    cudaFuncSetAttribute(hmma_fused, cudaFuncAttributeMaxDynamicSharedMemorySize, SM_TOTAL);

    init_kernel<<<(NROWS + 255) / 256, 256>>>(out, out_size);
    prep_kernel<<<(int)PREP_BLOCKS, 256>>>(input, weight, target, tvec);

    {   // fused exp-sum GEMM over all regions
        dim3 grid(RT, YTOT);              // 64 x 394
        hmma_fused<<<grid, 256, SM_TOTAL>>>(bias);
    }

    assemble_kernel<<<(NROWS + 255) / 256, 256>>>(target, bias, tbias, out, out_size);
}

// round 15
// speedup vs baseline: 1.3093x; 1.0243x over previous
#include <cuda_runtime.h>
#include <cuda_fp16.h>
#include <math.h>
#include <stdint.h>

#define NROWS    8192
#define DIM      1024
#define NCLASSES 50257
#define CUT0     4000
#define CUT1     20000
#define MGUARD   20.0f

#define MT  128
#define NT  128
#define BK  64
#define NCH (DIM / BK)            /* 16 k-chunks */
#define RT  (NROWS / MT)          /* 64 row tiles */
#define COLS_PAD 50688

#define YT_HEAD 32
#define YT_T1   125
#define YT_T2   237
#define YTOT    (YT_HEAD + YT_T1 + YT_T2)   /* 394 */

#define STAGE_BYTES 32768         /* A 16KB + B 16KB per stage */
#define NSTAGE 2
#define SM_TOTAL (NSTAGE * STAGE_BYTES)     /* 64KB -> 3 CTAs/SM */

#define SW128(o) ((o) ^ (((o) >> 3) & 0x70))

/* prep kernel block partition (small jobs first so they hide under cvt) */
#define ZERO_BLOCKS 32
#define SCAN_BLOCKS 1
#define EB_BLOCKS   50                                          /* 50*256*4 >= 50688 */
#define DOT_BLOCKS  (NROWS / 8)                                 /* 1024 */
#define CVTA_BLOCKS (((long)NROWS * DIM / 16 + 255) / 256)      /* 2048 */
#define CVTW_BLOCKS (((long)COLS_PAD * DIM / 16 + 255) / 256)   /* 12672 */
#define B_ZERO  0
#define B_SCAN  (B_ZERO + ZERO_BLOCKS)
#define B_EB    (B_SCAN + SCAN_BLOCKS)
#define B_DOT   (B_EB + EB_BLOCKS)
#define B_CVTA  (B_DOT + DOT_BLOCKS)
#define B_CVTW  (B_CVTA + CVTA_BLOCKS)
#define PREP_BLOCKS (B_CVTW + CVTW_BLOCKS)

// ---------------- device scratch ----------------
__device__ __align__(256) __half g_A16[(size_t)NROWS * DIM];
__device__ __align__(256) __half g_W16[(size_t)COLS_PAD * DIM];
__device__ float g_eb[COLS_PAD];
__device__ float g_head[NROWS];
__device__ float g_t1[NROWS];
__device__ float g_t2[NROWS];
__device__ float g_dwt[NROWS];
__device__ float g_d0[NROWS];
__device__ float g_d1[NROWS];
__device__ int   g_rows_c1[NROWS];
__device__ int   g_rows_c2[NROWS];
__device__ int   g_cnt[2];

// ---------------- PTX helpers ----------------
__device__ __forceinline__ uint32_t smem_u32(const void* p) {
    uint32_t a;
    asm("{ .reg .u64 t; cvta.to.shared.u64 t, %1; cvt.u32.u64 %0, t; }" : "=r"(a) : "l"(p));
    return a;
}
__device__ __forceinline__ void cp16(uint32_t dst, const void* src) {
    asm volatile("cp.async.cg.shared.global [%0], [%1], 16;" :: "r"(dst), "l"(src) : "memory");
}
__device__ __forceinline__ void cp_commit() {
    asm volatile("cp.async.commit_group;" ::: "memory");
}
template <int N>
__device__ __forceinline__ void cp_wait() {
    asm volatile("cp.async.wait_group %0;" :: "n"(N) : "memory");
}
__device__ __forceinline__ void ldm_x4(uint32_t* r, uint32_t addr) {
    asm volatile("ldmatrix.sync.aligned.m8n8.x4.shared.b16 {%0,%1,%2,%3}, [%4];"
                 : "=r"(r[0]), "=r"(r[1]), "=r"(r[2]), "=r"(r[3]) : "r"(addr));
}
__device__ __forceinline__ void ldm_x4_t(uint32_t* r, uint32_t addr) {
    asm volatile("ldmatrix.sync.aligned.m8n8.x4.trans.shared.b16 {%0,%1,%2,%3}, [%4];"
                 : "=r"(r[0]), "=r"(r[1]), "=r"(r[2]), "=r"(r[3]) : "r"(addr));
}
__device__ __forceinline__ void mma_fp16h(uint32_t* c, const uint32_t* a, const uint32_t* b) {
    asm volatile(
        "mma.sync.aligned.m16n8k16.row.col.f16.f16.f16.f16 "
        "{%0,%1}, {%2,%3,%4,%5}, {%6,%7}, {%0,%1};"
        : "+r"(c[0]), "+r"(c[1])
        : "r"(a[0]), "r"(a[1]), "r"(a[2]), "r"(a[3]), "r"(b[0]), "r"(b[1]));
}

// ---------------- prep: zero + scan-classify + eb + dots + cvt ----------------
__device__ __forceinline__ uint32_t pack2hf(float a, float b) {
    __half2 t = __floats2half2_rn(a, b);
    return *reinterpret_cast<uint32_t*>(&t);
}
__device__ __forceinline__ void cvt16(const float* __restrict__ src, __half* __restrict__ dst,
                                      long i, long n_src) {
    uint4 o;
    if (i < n_src) {
        float4 v0 = ((const float4*)src)[i / 4];
        float4 v1 = ((const float4*)src)[i / 4 + 1];
        float4 v2 = ((const float4*)src)[i / 4 + 2];
        float4 v3 = ((const float4*)src)[i / 4 + 3];
        uint4 p;
        p.x = pack2hf(v0.x, v0.y); p.y = pack2hf(v0.z, v0.w);
        p.z = pack2hf(v1.x, v1.y); p.w = pack2hf(v1.z, v1.w);
        o = p;
        *((uint4*)(dst + i)) = o;
        p.x = pack2hf(v2.x, v2.y); p.y = pack2hf(v2.z, v2.w);
        p.z = pack2hf(v3.x, v3.y); p.w = pack2hf(v3.z, v3.w);
        *((uint4*)(dst + i + 8)) = p;
    } else {
        o = make_uint4(0, 0, 0, 0);
        *((uint4*)(dst + i)) = o;
        *((uint4*)(dst + i + 8)) = o;
    }
}
__global__ void prep_kernel(const float* __restrict__ input,
                            const float* __restrict__ weight,
                            const int*   __restrict__ target,
                            const float* __restrict__ bias,
                            const float* __restrict__ tvec,
                            float* __restrict__ out, int out_size) {
    long bx = blockIdx.x;
    int tid = threadIdx.x;
    if (bx < B_SCAN) {
        // zero accumulators + loss slot
        int r = (int)bx * 256 + tid;
        g_head[r] = 0.f; g_t1[r] = 0.f; g_t2[r] = 0.f;
        if (bx == 0 && tid == 0 && out_size > NROWS) out[NROWS] = 0.f;
    } else if (bx < B_EB) {
        // deterministic single-block scan classify (no pre-zeroed counters)
        __shared__ int sc1[256], sc2[256];
        const int t0 = tid * 32;
        int c1 = 0, c2 = 0;
        for (int i = 0; i < 32; i++) {
            int t = target[t0 + i];
            c1 += (t >= CUT0) && (t < CUT1);
            c2 += (t >= CUT1);
        }
        sc1[tid] = c1; sc2[tid] = c2;
        __syncthreads();
        for (int off = 1; off < 256; off <<= 1) {
            int a1 = (tid >= off) ? sc1[tid - off] : 0;
            int a2 = (tid >= off) ? sc2[tid - off] : 0;
            __syncthreads();
            sc1[tid] += a1; sc2[tid] += a2;
            __syncthreads();
        }
        int o1 = sc1[tid] - c1, o2 = sc2[tid] - c2;
        for (int i = 0; i < 32; i++) {
            int t = target[t0 + i];
            if (t >= CUT1)      g_rows_c2[o2++] = t0 + i;
            else if (t >= CUT0) g_rows_c1[o1++] = t0 + i;
        }
        if (tid == 255) { g_cnt[0] = sc1[255]; g_cnt[1] = sc2[255]; }
    } else if (bx < B_DOT) {
        // eb[c] = exp(bias[c] - MGUARD), 0 beyond NCLASSES
        int c0 = ((int)(bx - B_EB) * 256 + tid) * 4;
#pragma unroll
        for (int q = 0; q < 4; q++) {
            int c = c0 + q;
            if (c < COLS_PAD)
                g_eb[c] = (c < NCLASSES) ? __expf(bias[c] - MGUARD) : 0.f;
        }
    } else if (bx < B_CVTA) {
        // per-row fp32 dots: input.weight[target], input.tv0, input.tv1
        int r = (int)(bx - B_DOT) * 8 + (tid >> 5);
        int lane = tid & 31;
        int t = target[r];
        const float4* a4   = (const float4*)(input + (size_t)r * DIM);
        const float4* wt4  = (const float4*)(weight + (size_t)t * DIM);
        const float4* tv04 = (const float4*)(tvec);
        const float4* tv14 = (const float4*)(tvec + DIM);
        float dwt = 0.f, d0 = 0.f, d1 = 0.f;
        for (int i = lane; i < DIM / 4; i += 32) {
            float4 a = a4[i], w = wt4[i], v0 = tv04[i], v1 = tv14[i];
            dwt += a.x * w.x  + a.y * w.y  + a.z * w.z  + a.w * w.w;
            d0  += a.x * v0.x + a.y * v0.y + a.z * v0.z + a.w * v0.w;
            d1  += a.x * v1.x + a.y * v1.y + a.z * v1.z + a.w * v1.w;
        }
#pragma unroll
        for (int o = 16; o > 0; o >>= 1) {
            dwt += __shfl_xor_sync(0xffffffffu, dwt, o);
            d0  += __shfl_xor_sync(0xffffffffu, d0,  o);
            d1  += __shfl_xor_sync(0xffffffffu, d1,  o);
        }
        if (lane == 0) { g_dwt[r] = dwt; g_d0[r] = d0; g_d1[r] = d1; }
    } else if (bx < B_CVTW) {
        long i = ((bx - B_CVTA) * 256 + tid) * 16;
        if (i < (long)NROWS * DIM)
            cvt16(input, g_A16, i, (long)NROWS * DIM);
    } else {
        long i = ((bx - B_CVTW) * 256 + tid) * 16;
        if (i < (long)COLS_PAD * DIM)
            cvt16(weight, g_W16, i, (long)NCLASSES * DIM);
    }
}

// ---------------- fused HMMA exp-sum GEMM (R11 mainloop, eb epilogue) ----------------
__global__ void __launch_bounds__(256, 3)
hmma_fused()
{
    extern __shared__ char smem[];
    const uint32_t sb = smem_u32(smem);
    const int tid = threadIdx.x;
    const int wid = tid >> 5;
    const int lane = tid & 31;

    // ---- region decode ----
    int ty = blockIdx.y;
    int col_lo, col_hi;
    const int* rowlist;
    int cnt;
    float* acc;
    if (ty < YT_HEAD) {
        col_lo = 0; col_hi = CUT0; rowlist = nullptr; cnt = NROWS; acc = g_head;
    } else if (ty < YT_HEAD + YT_T1) {
        ty -= YT_HEAD;
        col_lo = CUT0; col_hi = CUT1; rowlist = g_rows_c1; cnt = g_cnt[0]; acc = g_t1;
    } else {
        ty -= YT_HEAD + YT_T1;
        col_lo = CUT1; col_hi = NCLASSES; rowlist = g_rows_c2; cnt = g_cnt[1]; acc = g_t2;
    }
    const int row0 = blockIdx.x * MT;
    if (row0 >= cnt) return;
    const int col0 = col_lo + ty * NT;

    // ---- compact cp.async setup ----
    const int r_a = tid >> 3;
    const int kc  = tid & 7;
    int arow_idx[4];
#pragma unroll
    for (int i = 0; i < 4; i++) {
        int rr = row0 + (tid >> 3) + 32 * i;
        if (rowlist) arow_idx[i] = rowlist[rr < cnt ? rr : cnt - 1];
        else         arow_idx[i] = rr;
    }
    const __half* bsrc0 = g_W16 + (size_t)(col0 + r_a) * DIM + kc * 8;
    const uint32_t adst0 = sb + SW128(r_a * 128 + kc * 16);
    const uint32_t bdst0 = sb + 16384 + SW128(r_a * 128 + kc * 16);

    // prologue: stages 0,1
#pragma unroll
    for (int s = 0; s < 2; s++) {
        const uint32_t st = s * STAGE_BYTES;
        const int kof = s * BK;
#pragma unroll
        for (int i = 0; i < 4; i++) {
            cp16(adst0 + 4096 * i + st, g_A16 + (size_t)arow_idx[i] * DIM + kc * 8 + kof);
            cp16(bdst0 + 4096 * i + st, bsrc0 + (size_t)32 * DIM * i + kof);
        }
        cp_commit();
    }

    // ---- warp fragment addressing ----
    const int wm = wid & 1;
    const int wn = wid >> 1;
    const int arow = wm * 64 + (lane & 15);
    const uint32_t a_xor = (arow & 7) << 4;
    const uint32_t a_kext = (lane >> 4) << 4;
    const int ln = lane & 7, sel = lane >> 3;
    const int brow = wn * 32 + ln + ((sel >> 1) << 3);
    const uint32_t b_xor = (uint32_t)ln << 4;
    const uint32_t b_kext = (sel & 1) << 4;

    uint32_t hfr[4][4][2];
#pragma unroll
    for (int mi = 0; mi < 4; mi++)
#pragma unroll
        for (int ni = 0; ni < 4; ni++) { hfr[mi][ni][0] = 0u; hfr[mi][ni][1] = 0u; }

    for (int ch = 0; ch < NCH; ch++) {
        if (ch < NCH - 1) cp_wait<1>(); else cp_wait<0>();
        __syncthreads();

        const uint32_t st = (ch & 1) * STAGE_BYTES;
        const uint32_t Ab = sb + st + (uint32_t)arow * 128;
        const uint32_t Bb = sb + st + 16384 + (uint32_t)brow * 128;

#pragma unroll
        for (int kk = 0; kk < 4; kk++) {
            uint32_t a[4][4], b[2][4];
            const uint32_t kbA = (kk * 32 + a_kext) ^ a_xor;
            const uint32_t kbB = (kk * 32 + b_kext) ^ b_xor;
#pragma unroll
            for (int mi = 0; mi < 4; mi++)
                ldm_x4(a[mi], Ab + mi * 2048 + kbA);
#pragma unroll
            for (int nt = 0; nt < 2; nt++)
                ldm_x4_t(b[nt], Bb + nt * 2048 + kbB);
#pragma unroll
            for (int mi = 0; mi < 4; mi++)
#pragma unroll
                for (int ni = 0; ni < 4; ni++)
                    mma_fp16h(hfr[mi][ni], a[mi], &b[ni >> 1][(ni & 1) * 2]);
        }
        __syncthreads();

        if (ch + 2 < NCH) {
            const int kof = (ch + 2) * BK;
#pragma unroll
            for (int i = 0; i < 4; i++) {
                cp16(adst0 + 4096 * i + st, g_A16 + (size_t)arow_idx[i] * DIM + kc * 8 + kof);
                cp16(bdst0 + 4096 * i + st, bsrc0 + (size_t)32 * DIM * i + kof);
            }
            cp_commit();
        }
    }

    // ---- epilogue: s += exp(logit) * eb[c] -> one atomic per row ----
    float* red = (float*)smem;
    if (tid < MT) red[tid] = 0.f;
    __syncthreads();

#pragma unroll
    for (int mi = 0; mi < 4; mi++) {
        const int rl = wm * 64 + mi * 16 + (lane >> 2);
        float s0 = 0.f, s1 = 0.f;
#pragma unroll
        for (int ni = 0; ni < 4; ni++) {
            const int cc = col0 + wn * 32 + ni * 8 + (lane & 3) * 2;
            float2 f01 = __half22float2(*(const __half2*)&hfr[mi][ni][0]);
            float2 f23 = __half22float2(*(const __half2*)&hfr[mi][ni][1]);
            if (cc < col_hi) {
                float e = g_eb[cc];
                s0 = fmaf(__expf(f01.x), e, s0);
                s1 = fmaf(__expf(f23.x), e, s1);
            }
            if (cc + 1 < col_hi) {
                float e = g_eb[cc + 1];
                s0 = fmaf(__expf(f01.y), e, s0);
                s1 = fmaf(__expf(f23.y), e, s1);
            }
        }
        s0 += __shfl_xor_sync(0xffffffffu, s0, 1);
        s0 += __shfl_xor_sync(0xffffffffu, s0, 2);
        s1 += __shfl_xor_sync(0xffffffffu, s1, 1);
        s1 += __shfl_xor_sync(0xffffffffu, s1, 2);
        if ((lane & 3) == 0) {
            atomicAdd(&red[rl], s0);
            atomicAdd(&red[rl + 8], s1);
        }
    }
    __syncthreads();

    if (tid < MT) {
        int rr = row0 + tid;
        if (rr < cnt) {
            int orow = rowlist ? rowlist[rr] : rr;
            atomicAdd(&acc[orow], red[tid]);
        }
    }
}

// ---------------- assemble: per-row combine + warp-reduced loss ----------------
__global__ void __launch_bounds__(256)
assemble_kernel(const int* __restrict__ target,
                const float* __restrict__ bias,
                const float* __restrict__ TB,
                float* __restrict__ out, int out_size)
{
    int r = blockIdx.x * blockDim.x + threadIdx.x;
    int lane = threadIdx.x & 31;
    float o = 0.f;
    if (r < NROWS) {
        int t = target[r];

        float tv0l = g_d0[r] + TB[0];
        float tv1l = g_d1[r] + TB[1];
        float head_sum = g_head[r] + __expf(tv0l - MGUARD) + __expf(tv1l - MGUARD);
        float head_lse = logf(head_sum) + MGUARD;

        int c = (t >= CUT0) + (t >= CUT1);
        float wt_logit = g_dwt[r] + bias[t];
        float gather = (c == 0) ? wt_logit : ((c == 1) ? tv0l : tv1l);
        float head_term = gather - head_lse;

        float tail_term = 0.f;
        if (c > 0) {
            float ts = (c == 1) ? g_t1[r] : g_t2[r];
            tail_term = wt_logit - (logf(ts) + MGUARD);
        }
        o = head_term + tail_term;
        if (r < out_size) out[r] = o;
    }
    if (out_size > NROWS) {
        float l = (r < NROWS) ? (-o / (float)NROWS) : 0.f;
#pragma unroll
        for (int s = 16; s > 0; s >>= 1)
            l += __shfl_xor_sync(0xffffffffu, l, s);
        if (lane == 0) atomicAdd(&out[NROWS], l);
    }
}

// ---------------- launch ----------------
extern "C" void kernel_launch(void* const* d_in, const int* in_sizes, int n_in,
                              void* d_out, int out_size)
{
    const float* input  = (const float*)d_in[0];
    const int*   target = (const int*)  d_in[1];
    const float* weight = (const float*)d_in[2];
    const float* bias   = (const float*)d_in[3];
    const float* tvec   = (const float*)d_in[4];
    const float* tbias  = (const float*)d_in[5];
    float* out = (float*)d_out;

    cudaFuncSetAttribute(hmma_fused, cudaFuncAttributeMaxDynamicSharedMemorySize, SM_TOTAL);

    prep_kernel<<<(int)PREP_BLOCKS, 256>>>(input, weight, target, bias, tvec, out, out_size);

    {   // fused exp-sum GEMM over all regions
        dim3 grid(RT, YTOT);              // 64 x 394
        hmma_fused<<<grid, 256, SM_TOTAL>>>();
    }

    assemble_kernel<<<(NROWS + 255) / 256, 256>>>(target, bias, tbias, out, out_size);
}